// round 14
// baseline (speedup 1.0000x reference)
#include <cuda_runtime.h>
#include <cuda_bf16.h>

// ODEFunc: per-point fused MLP forward + analytic gradient.
// R13 design point (59.9us: NPAIR=2 x f32x2, LDS.128 paired weights, DS
// factored + w3-folded backward, ds identity, branch-free ELU, 168 regs /
// 12 warps). R14: BLOCK-PARITY PHASE STAGGER via __noinline__ functions.
// FMA-pipe (~61Kcyc/SMSP) and MUFU (~46Kcyc) currently SUM to the measured
// wall: lockstepped warps serialize the pipes. Odd blocks run main-net
// before p-nets so SMSP co-resident warps (which come from different
// blocks) feed different pipes. noinline keeps one code copy (R12's
// forceinline duplication regressed). Results pass through per-thread smem
// scratch to dodge ABI struct-return-through-local.

using u64 = unsigned long long;

__device__ __forceinline__ u64 pk(float lo, float hi) {
    u64 r; asm("mov.b64 %0,{%1,%2};" : "=l"(r) : "f"(lo), "f"(hi)); return r;
}
__device__ __forceinline__ void upk(u64 v, float& lo, float& hi) {
    asm("mov.b64 {%0,%1},%2;" : "=f"(lo), "=f"(hi) : "l"(v));
}
__device__ __forceinline__ u64 fma2(u64 a, u64 b, u64 c) {
    u64 d; asm("fma.rn.f32x2 %0,%1,%2,%3;" : "=l"(d) : "l"(a), "l"(b), "l"(c)); return d;
}
__device__ __forceinline__ u64 mul2(u64 a, u64 b) {
    u64 d; asm("mul.rn.f32x2 %0,%1,%2;" : "=l"(d) : "l"(a), "l"(b)); return d;
}
__device__ __forceinline__ u64 add2(u64 a, u64 b) {
    u64 d; asm("add.rn.f32x2 %0,%1,%2;" : "=l"(d) : "l"(a), "l"(b)); return d;
}

#define MONE2 0xBF800000BF800000ULL  // (-1.0f, -1.0f)

__device__ __forceinline__ float tanh_fast(float x) {
    float r; asm("tanh.approx.f32 %0,%1;" : "=f"(r) : "f"(x)); return r;
}
__device__ __forceinline__ float exp_fast(float x) {
    float r; asm("ex2.approx.f32 %0,%1;" : "=f"(r) : "f"(x * 1.4426950408889634f)); return r;
}
__device__ __forceinline__ u64 tanh2(u64 v) {
    float a, b; upk(v, a, b);
    return pk(tanh_fast(a), tanh_fast(b));
}
// branch-free ELU: max(x, exp(min(x,0)) - 1); exact for x>0 since ex2(0)=1
__device__ __forceinline__ u64 elu2(u64 v) {
    float a, b; upk(v, a, b);
    a = fmaxf(a, exp_fast(fminf(a, 0.f)) - 1.f);
    b = fmaxf(b, exp_fast(fminf(b, 0.f)) - 1.f);
    return pk(a, b);
}
// DS including the mean-1/2: ds = 0.125*(1 - tanh^2(0.25*tanh(z/2)+0.25))
__device__ __forceinline__ float ds_half(float z) {
    float t1 = tanh_fast(0.5f * z);
    float t2 = tanh_fast(fmaf(0.25f, t1, 0.25f));
    return fmaf(t2 * t2, -0.125f, 0.125f);
}

__device__ __forceinline__ ulonglong2 lds128(const u64* p) {
    return *reinterpret_cast<const ulonglong2*>(p);
}

#define NPAIR 2
#define NTHR 128

// wsm layout (same as R13):
//   0: W0(16)  16: B0(8)  24: W1(64)  88: B1(8)  96: W2(32)  128: B2(4)
//   132: PW1(32)  164: PB1(16)  180: PW2(128)  308: PB2(16)
//   324: PW3(16)  340: PB3(2)   344: PW2T'(128, pre-scaled by pW3)

// ---- p nets (NV=2), forward + analytic backward -> res[k*NTHR], k=0..3 ----
// res: 0:G0[0] 1:G0[1] 2:G1[0] 3:G1[1]
__device__ __noinline__ void pnets_fn(const u64* __restrict__ wsm,
                                      u64 X0a, u64 X0b, u64 X1a, u64 X1b,
                                      u64* __restrict__ res)
{
    const u64* PW1  = wsm + 132;
    const u64* PB1  = wsm + 164;
    const u64* PW2  = wsm + 180;
    const u64* PB2  = wsm + 308;
    const u64* PW3  = wsm + 324;
    const u64* PB3  = wsm + 340;
    const u64* PW2T = wsm + 344;

    u64 X0[NPAIR] = {X0a, X0b};
    u64 X1[NPAIR] = {X1a, X1b};

    u64 G0[NPAIR], G1[NPAIR];
    #pragma unroll
    for (int p = 0; p < NPAIR; p++) { G0[p] = 0ULL; G1[p] = 0ULL; }

    #pragma unroll
    for (int v = 0; v < 2; v++) {
        // f1 = tanh(x @ pW1^T + pb1)
        u64 f1[NPAIR][8];
        #pragma unroll
        for (int o = 0; o < 8; o++) {
            ulonglong2 w = lds128(&PW1[v * 16 + o * 2]);
            u64 b = PB1[v * 8 + o];
            #pragma unroll
            for (int p = 0; p < NPAIR; p++)
                f1[p][o] = tanh2(fma2(X1[p], w.y, fma2(X0[p], w.x, b)));
        }

        // f2 = tanh(f1 @ pW2^T + pb2)
        u64 f2[NPAIR][8];
        #pragma unroll
        for (int q = 0; q < 8; q++) {
            u64 a0[NPAIR], a1[NPAIR];
            u64 b = PB2[v * 8 + q];
            #pragma unroll
            for (int p = 0; p < NPAIR; p++) { a0[p] = b; a1[p] = 0ULL; }
            #pragma unroll
            for (int pp = 0; pp < 8; pp += 2) {
                ulonglong2 w = lds128(&PW2[v * 64 + q * 8 + pp]);
                #pragma unroll
                for (int p = 0; p < NPAIR; p++) {
                    a0[p] = fma2(f1[p][pp],     w.x, a0[p]);
                    a1[p] = fma2(f1[p][pp + 1], w.y, a1[p]);
                }
            }
            #pragma unroll
            for (int p = 0; p < NPAIR; p++) f2[p][q] = tanh2(add2(a0[p], a1[p]));
        }

        // z = f2 . pW3 + pb3 ; DS = 0.5*s(1-s) (independent of backward)
        u64 DS[NPAIR];
        {
            u64 a0[NPAIR], a1[NPAIR];
            u64 b = PB3[v];
            #pragma unroll
            for (int p = 0; p < NPAIR; p++) { a0[p] = b; a1[p] = 0ULL; }
            #pragma unroll
            for (int pp = 0; pp < 8; pp += 2) {
                ulonglong2 w = lds128(&PW3[v * 8 + pp]);
                #pragma unroll
                for (int p = 0; p < NPAIR; p++) {
                    a0[p] = fma2(f2[p][pp],     w.x, a0[p]);
                    a1[p] = fma2(f2[p][pp + 1], w.y, a1[p]);
                }
            }
            #pragma unroll
            for (int p = 0; p < NPAIR; p++) {
                float za, zb; upk(add2(a0[p], a1[p]), za, zb);
                DS[p] = pk(ds_half(za), ds_half(zb));
            }
        }

        // gq'_q = (f2_q^2 - 1)  (w3 folded into PW2T'; DS factored out)
        #pragma unroll
        for (int q = 0; q < 8; q++)
            #pragma unroll
            for (int p = 0; p < NPAIR; p++)
                f2[p][q] = fma2(f2[p][q], f2[p][q], MONE2);

        // PG_p = sum_pp [(sum_q gq'_q W2T'[pp,q]) * (f1_pp^2-1)] * pW1[pp,:]
        u64 PG0[NPAIR], PG1[NPAIR];
        #pragma unroll
        for (int p = 0; p < NPAIR; p++) { PG0[p] = 0ULL; PG1[p] = 0ULL; }
        #pragma unroll
        for (int pp = 0; pp < 8; pp++) {
            u64 a0[NPAIR], a1[NPAIR];
            #pragma unroll
            for (int p = 0; p < NPAIR; p++) { a0[p] = 0ULL; a1[p] = 0ULL; }
            #pragma unroll
            for (int q = 0; q < 8; q += 2) {
                ulonglong2 w = lds128(&PW2T[v * 64 + pp * 8 + q]);
                #pragma unroll
                for (int p = 0; p < NPAIR; p++) {
                    a0[p] = fma2(f2[p][q],     w.x, a0[p]);
                    a1[p] = fma2(f2[p][q + 1], w.y, a1[p]);
                }
            }
            ulonglong2 w1p = lds128(&PW1[v * 16 + pp * 2]);
            #pragma unroll
            for (int p = 0; p < NPAIR; p++) {
                u64 u1 = fma2(f1[p][pp], f1[p][pp], MONE2);
                u64 gpv = mul2(add2(a0[p], a1[p]), u1);
                PG0[p] = fma2(gpv, w1p.x, PG0[p]);
                PG1[p] = fma2(gpv, w1p.y, PG1[p]);
            }
        }
        #pragma unroll
        for (int p = 0; p < NPAIR; p++) {
            G0[p] = fma2(DS[p], PG0[p], G0[p]);
            G1[p] = fma2(DS[p], PG1[p], G1[p]);
        }
    }

    res[0 * NTHR] = G0[0];
    res[1 * NTHR] = G0[1];
    res[2 * NTHR] = G1[0];
    res[3 * NTHR] = G1[1];
}

// ---- main net -> res[k*NTHR], k=0..5: m2v[0],m2v[1],magA[0],magA[1],magD[0],magD[1]
__device__ __noinline__ void mainnet_fn(const u64* __restrict__ wsm,
                                        u64 X0a, u64 X0b, u64 X1a, u64 X1b,
                                        u64* __restrict__ res)
{
    const u64* W0 = wsm;
    const u64* B0 = wsm + 16;
    const u64* W1 = wsm + 24;
    const u64* B1 = wsm + 88;
    const u64* W2 = wsm + 96;
    const u64* B2 = wsm + 128;

    u64 X0[NPAIR] = {X0a, X0b};
    u64 X1[NPAIR] = {X1a, X1b};

    u64 h0[NPAIR][8];
    #pragma unroll
    for (int i = 0; i < 8; i++) {
        ulonglong2 w = lds128(&W0[i * 2]);
        u64 b = B0[i];
        #pragma unroll
        for (int p = 0; p < NPAIR; p++)
            h0[p][i] = elu2(fma2(X1[p], w.y, fma2(X0[p], w.x, b)));
    }

    u64 h1[NPAIR][8];
    #pragma unroll
    for (int i = 0; i < 8; i++) {
        u64 a0[NPAIR], a1[NPAIR];
        u64 b = B1[i];
        #pragma unroll
        for (int p = 0; p < NPAIR; p++) { a0[p] = b; a1[p] = 0ULL; }
        #pragma unroll
        for (int j = 0; j < 8; j += 2) {
            ulonglong2 w = lds128(&W1[i * 8 + j]);
            #pragma unroll
            for (int p = 0; p < NPAIR; p++) {
                a0[p] = fma2(h0[p][j],     w.x, a0[p]);
                a1[p] = fma2(h0[p][j + 1], w.y, a1[p]);
            }
        }
        #pragma unroll
        for (int p = 0; p < NPAIR; p++) h1[p][i] = elu2(add2(a0[p], a1[p]));
    }

    u64 bb[NPAIR][4];
    #pragma unroll
    for (int i = 0; i < 4; i++) {
        u64 a0[NPAIR], a1[NPAIR];
        u64 b = B2[i];
        #pragma unroll
        for (int p = 0; p < NPAIR; p++) { a0[p] = b; a1[p] = 0ULL; }
        #pragma unroll
        for (int j = 0; j < 8; j += 2) {
            ulonglong2 w = lds128(&W2[i * 8 + j]);
            #pragma unroll
            for (int p = 0; p < NPAIR; p++) {
                a0[p] = fma2(h1[p][j],     w.x, a0[p]);
                a1[p] = fma2(h1[p][j + 1], w.y, a1[p]);
            }
        }
        #pragma unroll
        for (int p = 0; p < NPAIR; p++) bb[p][i] = add2(a0[p], a1[p]);
    }
    #pragma unroll
    for (int p = 0; p < NPAIR; p++) {
        res[(0 * NPAIR + p) * NTHR] = fma2(bb[p][0], bb[p][1], mul2(bb[p][2], bb[p][3])); // m2v
        res[(1 * NPAIR + p) * NTHR] = fma2(bb[p][0], bb[p][0], mul2(bb[p][2], bb[p][2])); // magA
        res[(2 * NPAIR + p) * NTHR] = fma2(bb[p][1], bb[p][1], mul2(bb[p][3], bb[p][3])); // magD
    }
}

__global__ void __launch_bounds__(NTHR, 3)
odefunc_kernel(const float* __restrict__ x,
               const float* __restrict__ mW0, const float* __restrict__ mb0,
               const float* __restrict__ mW1, const float* __restrict__ mb1,
               const float* __restrict__ mW2, const float* __restrict__ mb2,
               const float* __restrict__ pW1, const float* __restrict__ pb1,
               const float* __restrict__ pW2, const float* __restrict__ pb2,
               const float* __restrict__ pW3, const float* __restrict__ pb3,
               float* __restrict__ out, int npairs)
{
    __shared__ __align__(16) u64 wsm[472];
    __shared__ u64 res[10 * NTHR];   // per-thread scratch: G(4) + mags(6)
    {
        const float* srcs[12] = {mW0, mb0, mW1, mb1, mW2, mb2,
                                 pW1, pb1, pW2, pb2, pW3, pb3};
        const int offs[13] = {0, 16, 24, 88, 96, 128, 132, 164, 180, 308, 324, 340, 342};
        for (int idx = threadIdx.x; idx < 342; idx += blockDim.x) {
            int seg = 0;
            #pragma unroll
            for (int s2 = 0; s2 < 12; s2++)
                if (idx >= offs[s2 + 1]) seg = s2 + 1;
            float w = srcs[seg][idx - offs[seg]];
            wsm[idx] = pk(w, w);
        }
        // PW2T'[v*64 + pp*8 + q] = pW2[v, q, pp] * pW3[v, q]
        for (int idx = threadIdx.x; idx < 128; idx += blockDim.x) {
            int v = idx >> 6, rem = idx & 63;
            int pp = rem >> 3, q = rem & 7;
            float w = pW2[v * 64 + q * 8 + pp] * pW3[v * 8 + q];
            wsm[344 + idx] = pk(w, w);
        }
    }
    __syncthreads();

    const int tid = threadIdx.x;
    const int base   = blockIdx.x * NTHR + tid;
    const int stride = gridDim.x * NTHR;

    int pi[NPAIR];
    bool valid[NPAIR];
    u64 X0[NPAIR], X1[NPAIR];
    #pragma unroll
    for (int p = 0; p < NPAIR; p++) {
        pi[p] = base + p * stride;
        valid[p] = pi[p] < npairs;
        if (valid[p]) {
            float4 xx = reinterpret_cast<const float4*>(x)[pi[p]];
            X0[p] = pk(xx.x, xx.z);
            X1[p] = pk(xx.y, xx.w);
        } else {
            X0[p] = 0ULL; X1[p] = 0ULL;
        }
    }

    u64* myG = res + tid;               // [k*NTHR], k=0..3
    u64* myM = res + 4 * NTHR + tid;    // [k*NTHR], k=0..5

    // Block-parity phase stagger: SMSP co-resident warps come from different
    // blocks; odd blocks run the FMA-heavy main net while even blocks are in
    // the MUFU-heavy p-net phases, and vice versa.
    if (blockIdx.x & 1) {
        mainnet_fn(wsm, X0[0], X0[1], X1[0], X1[1], myM);
        pnets_fn  (wsm, X0[0], X0[1], X1[0], X1[1], myG);
    } else {
        pnets_fn  (wsm, X0[0], X0[1], X1[0], X1[1], myG);
        mainnet_fn(wsm, X0[0], X0[1], X1[0], X1[1], myM);
    }

    // out0 = magA*G0 + m2*G1; out1 = m2*G0 + magD*G1   (0.5 already in DS)
    #pragma unroll
    for (int p = 0; p < NPAIR; p++) {
        if (!valid[p]) continue;
        u64 G0 = myG[(0 * NPAIR + p >= 2 ? 1 : 0) * NTHR];  // placeholder avoided below
        (void)G0;
    }
    {
        u64 G0a = myG[0 * NTHR], G0b = myG[1 * NTHR];
        u64 G1a = myG[2 * NTHR], G1b = myG[3 * NTHR];
        u64 m2a = myM[0 * NTHR], m2b = myM[1 * NTHR];
        u64 mAa = myM[2 * NTHR], mAb = myM[3 * NTHR];
        u64 mDa = myM[4 * NTHR], mDb = myM[5 * NTHR];

        u64 G0[NPAIR]  = {G0a, G0b};
        u64 G1[NPAIR]  = {G1a, G1b};
        u64 m2v[NPAIR] = {m2a, m2b};
        u64 mA[NPAIR]  = {mAa, mAb};
        u64 mD[NPAIR]  = {mDa, mDb};

        #pragma unroll
        for (int p = 0; p < NPAIR; p++) {
            if (!valid[p]) continue;
            u64 o0 = fma2(mA[p], G0[p], mul2(m2v[p], G1[p]));
            u64 o1 = fma2(m2v[p], G0[p], mul2(mD[p], G1[p]));
            float a0, b0c, a1, b1c;
            upk(o0, a0, b0c);
            upk(o1, a1, b1c);
            reinterpret_cast<float4*>(out)[pi[p]] = make_float4(a0, a1, b0c, b1c);
        }
    }
}

extern "C" void kernel_launch(void* const* d_in, const int* in_sizes, int n_in,
                              void* d_out, int out_size)
{
    const float* x   = (const float*)d_in[1];
    const float* mW0 = (const float*)d_in[2];
    const float* mb0 = (const float*)d_in[3];
    const float* mW1 = (const float*)d_in[4];
    const float* mb1 = (const float*)d_in[5];
    const float* mW2 = (const float*)d_in[6];
    const float* mb2 = (const float*)d_in[7];
    const float* pW1 = (const float*)d_in[8];
    const float* pb1 = (const float*)d_in[9];
    const float* pW2 = (const float*)d_in[10];
    const float* pb2 = (const float*)d_in[11];
    const float* pW3 = (const float*)d_in[12];
    const float* pb3 = (const float*)d_in[13];

    int B = in_sizes[1] / 2;       // x is (B, 2)
    int npairs = B / 2;
    int threads = NTHR;
    int tot_threads = (npairs + NPAIR - 1) / NPAIR;
    int blocks = (tot_threads + threads - 1) / threads;

    odefunc_kernel<<<blocks, threads>>>(x, mW0, mb0, mW1, mb1, mW2, mb2,
                                        pW1, pb1, pW2, pb2, pW3, pb3,
                                        (float*)d_out, npairs);
}

// round 17
// speedup vs baseline: 1.0694x; 1.0694x over previous
#include <cuda_runtime.h>
#include <cuda_bf16.h>

// ODEFunc: per-point fused MLP forward + analytic gradient.
// R13 design point (59.9us best): NPAIR=2 x f32x2, LDS.128 paired weights,
// DS-factored + w3-folded backward, 168 regs / 12 warps, main net last.
// R17 (f16 tanh reverted -- failed 1.6e-3):
//  - shifted ELU: elu(x)+1 = max(x+1, min(exp(x),1)); +1 shifts folded into
//    biases (b0+1, b1-rowsum(W1)+1, b2-rowsum(W2)) at smem-fill time.
//    1 fewer op/scalar, packed fma computes the ex2 argument. Exact.
//  - DS cubic: ds = 0.5 s(1-s), s=sigma(sigma(z)) == cubic in t=tanh(z/2)
//    (range-limited, near-linear). 1 tanh + packed 3xfma2 replaces the
//    2-tanh sigmoid chain. Interp err <= 4e-5 abs (~4e-4 rel on grad).

using u64 = unsigned long long;

__device__ __forceinline__ u64 pk(float lo, float hi) {
    u64 r; asm("mov.b64 %0,{%1,%2};" : "=l"(r) : "f"(lo), "f"(hi)); return r;
}
__device__ __forceinline__ void upk(u64 v, float& lo, float& hi) {
    asm("mov.b64 {%0,%1},%2;" : "=f"(lo), "=f"(hi) : "l"(v));
}
__device__ __forceinline__ u64 fma2(u64 a, u64 b, u64 c) {
    u64 d; asm("fma.rn.f32x2 %0,%1,%2,%3;" : "=l"(d) : "l"(a), "l"(b), "l"(c)); return d;
}
__device__ __forceinline__ u64 mul2(u64 a, u64 b) {
    u64 d; asm("mul.rn.f32x2 %0,%1,%2;" : "=l"(d) : "l"(a), "l"(b)); return d;
}
__device__ __forceinline__ u64 add2(u64 a, u64 b) {
    u64 d; asm("add.rn.f32x2 %0,%1,%2;" : "=l"(d) : "l"(a), "l"(b)); return d;
}

#define MONE2   0xBF800000BF800000ULL  // (-1.0f, -1.0f)
#define LOG2E2  0x3FB8AA3B3FB8AA3BULL  // ( log2e,  log2e)
#define MLOG2E2 0xBFB8AA3BBFB8AA3BULL  // (-log2e, -log2e)
#define HALFC2  0x3F0000003F000000ULL  // (0.5f, 0.5f)

__device__ __forceinline__ float tanh_fast(float x) {
    float r; asm("tanh.approx.f32 %0,%1;" : "=f"(r) : "f"(x)); return r;
}
// Shifted branch-free ELU: input acc1 = acc+1 (bias pre-shifted).
// elu(acc)+1 = max(acc+1, min(exp(acc), 1)).  exp(acc) = ex2(acc1*log2e - log2e).
__device__ __forceinline__ u64 elu2s(u64 acc1) {
    u64 e = fma2(acc1, LOG2E2, MLOG2E2);
    float ea, eb; upk(e, ea, eb);
    asm("ex2.approx.f32 %0,%0;" : "+f"(ea));
    asm("ex2.approx.f32 %0,%0;" : "+f"(eb));
    float a1, b1; upk(acc1, a1, b1);
    return pk(fmaxf(a1, fminf(ea, 1.f)), fmaxf(b1, fminf(eb, 1.f)));
}
// Packed DS (incl. mean-0.5): ds = P(tanh(z/2)), cubic interp on t in [-1,1].
// P(t) = c0 + c1 t + c2 t^2 + c3 t^3, max abs err ~4e-5 on ds~0.1.
__device__ __forceinline__ u64 ds2(u64 z) {
    float za, zb; upk(mul2(z, HALFC2), za, zb);
    u64 tv = pk(tanh_fast(za), tanh_fast(zb));
    u64 c3 = pk(0.00104119f, 0.00104119f);
    u64 c2 = pk(-0.00583031f, -0.00583031f);
    u64 c1 = pk(-0.01438819f, -0.01438819f);
    u64 c0 = pk(0.11748331f, 0.11748331f);
    u64 r = fma2(tv, c3, c2);
    r = fma2(tv, r, c1);
    return fma2(tv, r, c0);
}

__device__ __forceinline__ u64 tanh2(u64 v) {
    float a, b; upk(v, a, b);
    return pk(tanh_fast(a), tanh_fast(b));
}

__device__ __forceinline__ ulonglong2 lds128(const u64* p) {
    return *reinterpret_cast<const ulonglong2*>(p);
}

#define NPAIR 2
#define NTHR 128

__global__ void __launch_bounds__(NTHR, 3)
odefunc_kernel(const float* __restrict__ x,
               const float* __restrict__ mW0, const float* __restrict__ mb0,
               const float* __restrict__ mW1, const float* __restrict__ mb1,
               const float* __restrict__ mW2, const float* __restrict__ mb2,
               const float* __restrict__ pW1, const float* __restrict__ pb1,
               const float* __restrict__ pW2, const float* __restrict__ pb2,
               const float* __restrict__ pW3, const float* __restrict__ pb3,
               float* __restrict__ out, int npairs)
{
    // [0..342): segmented weights (replicated f32x2), biases PRE-SHIFTED for
    // the shifted-ELU identity; [344..472): PW2 transposed, pre-scaled by pW3
    __shared__ __align__(16) u64 wsm[472];
    {
        const float* srcs[12] = {mW0, mb0, mW1, mb1, mW2, mb2,
                                 pW1, pb1, pW2, pb2, pW3, pb3};
        const int offs[13] = {0, 16, 24, 88, 96, 128, 132, 164, 180, 308, 324, 340, 342};
        for (int idx = threadIdx.x; idx < 342; idx += blockDim.x) {
            int seg = 0;
            #pragma unroll
            for (int s2 = 0; s2 < 12; s2++)
                if (idx >= offs[s2 + 1]) seg = s2 + 1;
            int k = idx - offs[seg];
            float w = srcs[seg][k];
            if (seg == 1) {                       // B0' = b0 + 1
                w += 1.f;
            } else if (seg == 3) {                // B1' = b1 - rowsum(W1) + 1
                float s = 0.f;
                for (int j = 0; j < 8; j++) s += mW1[k * 8 + j];
                w = w - s + 1.f;
            } else if (seg == 5) {                // B2' = b2 - rowsum(W2)
                float s = 0.f;
                for (int j = 0; j < 8; j++) s += mW2[k * 8 + j];
                w = w - s;
            }
            wsm[idx] = pk(w, w);
        }
        // PW2T'[v*64 + pp*8 + q] = pW2[v, q, pp] * pW3[v, q]
        for (int idx = threadIdx.x; idx < 128; idx += blockDim.x) {
            int v = idx >> 6, rem = idx & 63;
            int pp = rem >> 3, q = rem & 7;
            float w = pW2[v * 64 + q * 8 + pp] * pW3[v * 8 + q];
            wsm[344 + idx] = pk(w, w);
        }
    }
    __syncthreads();

    const u64* W0   = wsm;         // 16 : [i*2+j]
    const u64* B0   = wsm + 16;    // 8   (pre-shifted +1)
    const u64* W1   = wsm + 24;    // 64 : [i*8+j]
    const u64* B1   = wsm + 88;    // 8   (b1 - rowsum + 1)
    const u64* W2   = wsm + 96;    // 32 : [i*8+j]
    const u64* B2   = wsm + 128;   // 4   (b2 - rowsum)
    const u64* PW1  = wsm + 132;   // 32 : [v*16+o*2+i]
    const u64* PB1  = wsm + 164;   // 16 : [v*8+o]
    const u64* PW2  = wsm + 180;   // 128: [v*64+q*8+p]
    const u64* PB2  = wsm + 308;   // 16 : [v*8+q]
    const u64* PW3  = wsm + 324;   // 16 : [v*8+p]
    const u64* PB3  = wsm + 340;   // 2  : [v]
    const u64* PW2T = wsm + 344;   // 128: [v*64+p*8+q], pre-scaled by w3_q

    const int tid = threadIdx.x;
    const int base   = blockIdx.x * NTHR + tid;
    const int stride = gridDim.x * NTHR;

    int pi[NPAIR];
    bool valid[NPAIR];
    u64 X0[NPAIR], X1[NPAIR];
    #pragma unroll
    for (int p = 0; p < NPAIR; p++) {
        pi[p] = base + p * stride;
        valid[p] = pi[p] < npairs;
        if (valid[p]) {
            float4 xx = reinterpret_cast<const float4*>(x)[pi[p]];
            X0[p] = pk(xx.x, xx.z);
            X1[p] = pk(xx.y, xx.w);
        } else {
            X0[p] = 0ULL; X1[p] = 0ULL;
        }
    }

    // ================= p nets (NV=2), forward + analytic backward =================
    u64 G0[NPAIR], G1[NPAIR];
    #pragma unroll
    for (int p = 0; p < NPAIR; p++) { G0[p] = 0ULL; G1[p] = 0ULL; }

    #pragma unroll
    for (int v = 0; v < 2; v++) {
        // f1 = tanh(x @ pW1^T + pb1)
        u64 f1[NPAIR][8];
        #pragma unroll
        for (int o = 0; o < 8; o++) {
            ulonglong2 w = lds128(&PW1[v * 16 + o * 2]);
            u64 b = PB1[v * 8 + o];
            #pragma unroll
            for (int p = 0; p < NPAIR; p++)
                f1[p][o] = tanh2(fma2(X1[p], w.y, fma2(X0[p], w.x, b)));
        }

        // f2 = tanh(f1 @ pW2^T + pb2)
        u64 f2[NPAIR][8];
        #pragma unroll
        for (int q = 0; q < 8; q++) {
            u64 a0[NPAIR], a1[NPAIR];
            u64 b = PB2[v * 8 + q];
            #pragma unroll
            for (int p = 0; p < NPAIR; p++) { a0[p] = b; a1[p] = 0ULL; }
            #pragma unroll
            for (int pp = 0; pp < 8; pp += 2) {
                ulonglong2 w = lds128(&PW2[v * 64 + q * 8 + pp]);
                #pragma unroll
                for (int p = 0; p < NPAIR; p++) {
                    a0[p] = fma2(f1[p][pp],     w.x, a0[p]);
                    a1[p] = fma2(f1[p][pp + 1], w.y, a1[p]);
                }
            }
            #pragma unroll
            for (int p = 0; p < NPAIR; p++) f2[p][q] = tanh2(add2(a0[p], a1[p]));
        }

        // z = f2 . pW3 + pb3 ; DS = packed cubic in tanh(z/2)
        u64 DS[NPAIR];
        {
            u64 a0[NPAIR], a1[NPAIR];
            u64 b = PB3[v];
            #pragma unroll
            for (int p = 0; p < NPAIR; p++) { a0[p] = b; a1[p] = 0ULL; }
            #pragma unroll
            for (int pp = 0; pp < 8; pp += 2) {
                ulonglong2 w = lds128(&PW3[v * 8 + pp]);
                #pragma unroll
                for (int p = 0; p < NPAIR; p++) {
                    a0[p] = fma2(f2[p][pp],     w.x, a0[p]);
                    a1[p] = fma2(f2[p][pp + 1], w.y, a1[p]);
                }
            }
            #pragma unroll
            for (int p = 0; p < NPAIR; p++)
                DS[p] = ds2(add2(a0[p], a1[p]));
        }

        // gq'_q = (f2_q^2 - 1)  (w3 folded into PW2T'; DS factored out;
        //                        sign cancels with gp's (f1^2-1))
        #pragma unroll
        for (int q = 0; q < 8; q++)
            #pragma unroll
            for (int p = 0; p < NPAIR; p++)
                f2[p][q] = fma2(f2[p][q], f2[p][q], MONE2);

        // PG_p = sum_pp [(sum_q gq'_q W2T'[pp,q]) * (f1_pp^2-1)] * pW1[pp,:]
        u64 PG0[NPAIR], PG1[NPAIR];
        #pragma unroll
        for (int p = 0; p < NPAIR; p++) { PG0[p] = 0ULL; PG1[p] = 0ULL; }
        #pragma unroll
        for (int pp = 0; pp < 8; pp++) {
            u64 a0[NPAIR], a1[NPAIR];
            #pragma unroll
            for (int p = 0; p < NPAIR; p++) { a0[p] = 0ULL; a1[p] = 0ULL; }
            #pragma unroll
            for (int q = 0; q < 8; q += 2) {
                ulonglong2 w = lds128(&PW2T[v * 64 + pp * 8 + q]);
                #pragma unroll
                for (int p = 0; p < NPAIR; p++) {
                    a0[p] = fma2(f2[p][q],     w.x, a0[p]);
                    a1[p] = fma2(f2[p][q + 1], w.y, a1[p]);
                }
            }
            ulonglong2 w1p = lds128(&PW1[v * 16 + pp * 2]);
            #pragma unroll
            for (int p = 0; p < NPAIR; p++) {
                u64 u1 = fma2(f1[p][pp], f1[p][pp], MONE2);
                u64 gpv = mul2(add2(a0[p], a1[p]), u1);
                PG0[p] = fma2(gpv, w1p.x, PG0[p]);
                PG1[p] = fma2(gpv, w1p.y, PG1[p]);
            }
        }
        // fold DS (incl. the 0.5 mean) in once per v
        #pragma unroll
        for (int p = 0; p < NPAIR; p++) {
            G0[p] = fma2(DS[p], PG0[p], G0[p]);
            G1[p] = fma2(DS[p], PG1[p], G1[p]);
        }
    }

    // ================= main net (last; shifted-ELU h' = h+1) =================
    u64 m2v[NPAIR], magA[NPAIR], magD[NPAIR];
    {
        u64 h0[NPAIR][8];   // h0' = h0 + 1
        #pragma unroll
        for (int i = 0; i < 8; i++) {
            ulonglong2 w = lds128(&W0[i * 2]);
            u64 b = B0[i];  // pre-shifted +1
            #pragma unroll
            for (int p = 0; p < NPAIR; p++)
                h0[p][i] = elu2s(fma2(X1[p], w.y, fma2(X0[p], w.x, b)));
        }

        u64 h1[NPAIR][8];   // h1' = h1 + 1
        #pragma unroll
        for (int i = 0; i < 8; i++) {
            u64 a0[NPAIR], a1[NPAIR];
            u64 b = B1[i];  // b1 - rowsum(W1) + 1
            #pragma unroll
            for (int p = 0; p < NPAIR; p++) { a0[p] = b; a1[p] = 0ULL; }
            #pragma unroll
            for (int j = 0; j < 8; j += 2) {
                ulonglong2 w = lds128(&W1[i * 8 + j]);
                #pragma unroll
                for (int p = 0; p < NPAIR; p++) {
                    a0[p] = fma2(h0[p][j],     w.x, a0[p]);
                    a1[p] = fma2(h0[p][j + 1], w.y, a1[p]);
                }
            }
            #pragma unroll
            for (int p = 0; p < NPAIR; p++) h1[p][i] = elu2s(add2(a0[p], a1[p]));
        }

        u64 bb[NPAIR][4];
        #pragma unroll
        for (int i = 0; i < 4; i++) {
            u64 a0[NPAIR], a1[NPAIR];
            u64 b = B2[i];  // b2 - rowsum(W2)
            #pragma unroll
            for (int p = 0; p < NPAIR; p++) { a0[p] = b; a1[p] = 0ULL; }
            #pragma unroll
            for (int j = 0; j < 8; j += 2) {
                ulonglong2 w = lds128(&W2[i * 8 + j]);
                #pragma unroll
                for (int p = 0; p < NPAIR; p++) {
                    a0[p] = fma2(h1[p][j],     w.x, a0[p]);
                    a1[p] = fma2(h1[p][j + 1], w.y, a1[p]);
                }
            }
            #pragma unroll
            for (int p = 0; p < NPAIR; p++) bb[p][i] = add2(a0[p], a1[p]);
        }
        #pragma unroll
        for (int p = 0; p < NPAIR; p++) {
            m2v[p]  = fma2(bb[p][0], bb[p][1], mul2(bb[p][2], bb[p][3]));
            magA[p] = fma2(bb[p][0], bb[p][0], mul2(bb[p][2], bb[p][2]));
            magD[p] = fma2(bb[p][1], bb[p][1], mul2(bb[p][3], bb[p][3]));
        }
    }

    // out0 = magA*G0 + m2*G1; out1 = m2*G0 + magD*G1   (0.5 already in DS)
    #pragma unroll
    for (int p = 0; p < NPAIR; p++) {
        if (!valid[p]) continue;
        u64 o0 = fma2(magA[p], G0[p], mul2(m2v[p], G1[p]));
        u64 o1 = fma2(m2v[p], G0[p], mul2(magD[p], G1[p]));
        float a0, b0c, a1, b1c;
        upk(o0, a0, b0c);
        upk(o1, a1, b1c);
        reinterpret_cast<float4*>(out)[pi[p]] = make_float4(a0, a1, b0c, b1c);
    }
}

extern "C" void kernel_launch(void* const* d_in, const int* in_sizes, int n_in,
                              void* d_out, int out_size)
{
    const float* x   = (const float*)d_in[1];
    const float* mW0 = (const float*)d_in[2];
    const float* mb0 = (const float*)d_in[3];
    const float* mW1 = (const float*)d_in[4];
    const float* mb1 = (const float*)d_in[5];
    const float* mW2 = (const float*)d_in[6];
    const float* mb2 = (const float*)d_in[7];
    const float* pW1 = (const float*)d_in[8];
    const float* pb1 = (const float*)d_in[9];
    const float* pW2 = (const float*)d_in[10];
    const float* pb2 = (const float*)d_in[11];
    const float* pW3 = (const float*)d_in[12];
    const float* pb3 = (const float*)d_in[13];

    int B = in_sizes[1] / 2;       // x is (B, 2)
    int npairs = B / 2;
    int threads = NTHR;
    int tot_threads = (npairs + NPAIR - 1) / NPAIR;
    int blocks = (tot_threads + threads - 1) / threads;

    odefunc_kernel<<<blocks, threads>>>(x, mW0, mb0, mW1, mb1, mW2, mb2,
                                        pW1, pb1, pW2, pb2, pW3, pb3,
                                        (float*)d_out, npairs);
}